// round 12
// baseline (speedup 1.0000x reference)
#include <cuda_runtime.h>
#include <cuda_bf16.h>
#include <cstdint>

// MrLoRA: out = x @ (W + sum_i coef_i B_i A_i)^T + b
// int8 IMMA split-precision path.
//   x ~= sx*(128*x1 + x0), W_eff ~= sw*(128*w1 + w0)   (s8 limbs, 14-bit)
//   out ~= sx*sw*(16384*acc_H + 128*acc_M) + bias
//   acc_H = x1*w1 ; acc_M = x1*w0 + x0*w1 (shared s32 accum); x0*w0 dropped.
// Legacy mma.sync only (harness PTX target compute_103 forbids tcgen05).

#define DIN   4096
#define DOUT  4096
#define MTOT  8192
#define QMAX  16250.0f

// ---- scratch (device globals; allocation-free rule) ----
__device__ float        g_wf[(size_t)DOUT * DIN];   // folded W_eff fp32
__device__ signed char  g_x1[(size_t)MTOT * DIN];
__device__ signed char  g_x0[(size_t)MTOT * DIN];
__device__ signed char  g_w1[(size_t)DOUT * DIN];
__device__ signed char  g_w0[(size_t)DOUT * DIN];
__device__ unsigned int g_xmax_bits;   // atomicMax of |x| bits (idempotent)
__device__ unsigned int g_wmax_bits;

// ---------------------------------------------------------------------------
// helpers
// ---------------------------------------------------------------------------
__device__ __forceinline__ uint32_t smem_u32(const void* p) {
    uint32_t a;
    asm("{ .reg .u64 t; cvta.to.shared.u64 t, %1; cvt.u32.u64 %0, t; }"
        : "=r"(a) : "l"(p));
    return a;
}
__device__ __forceinline__ void cp16(uint32_t dst, const void* src) {
    asm volatile("cp.async.cg.shared.global [%0], [%1], 16;"
                 :: "r"(dst), "l"(src) : "memory");
}
__device__ __forceinline__ void cp_commit() {
    asm volatile("cp.async.commit_group;" ::: "memory");
}
__device__ __forceinline__ void cp_wait1() {
    asm volatile("cp.async.wait_group 1;" ::: "memory");
}
__device__ __forceinline__ void ldsm_x4(uint32_t& r0, uint32_t& r1,
                                        uint32_t& r2, uint32_t& r3, uint32_t a) {
    asm volatile("ldmatrix.sync.aligned.m8n8.x4.shared.b16 {%0,%1,%2,%3}, [%4];"
                 : "=r"(r0), "=r"(r1), "=r"(r2), "=r"(r3) : "r"(a));
}
__device__ __forceinline__ void imma16832(int* d, const uint32_t* a,
                                          const uint32_t* b) {
    asm volatile(
        "mma.sync.aligned.m16n8k32.row.col.s32.s8.s8.s32 "
        "{%0,%1,%2,%3}, {%4,%5,%6,%7}, {%8,%9}, {%0,%1,%2,%3};"
        : "+r"(d[0]), "+r"(d[1]), "+r"(d[2]), "+r"(d[3])
        : "r"(a[0]), "r"(a[1]), "r"(a[2]), "r"(a[3]), "r"(b[0]), "r"(b[1]));
}

// ---------------------------------------------------------------------------
// 1) maxabs of x
// ---------------------------------------------------------------------------
__global__ __launch_bounds__(256) void xmax_kernel(const float* __restrict__ x) {
    const size_t stride = (size_t)gridDim.x * 256 * 4;
    size_t i = ((size_t)blockIdx.x * 256 + threadIdx.x) * 4;
    float m = 0.0f;
    for (; i < (size_t)MTOT * DIN; i += stride) {
        float4 v = *(const float4*)(x + i);
        m = fmaxf(m, fmaxf(fmaxf(fabsf(v.x), fabsf(v.y)),
                           fmaxf(fabsf(v.z), fabsf(v.w))));
    }
    __shared__ float red[256];
    red[threadIdx.x] = m;
    __syncthreads();
    for (int s = 128; s > 0; s >>= 1) {
        if (threadIdx.x < s) red[threadIdx.x] = fmaxf(red[threadIdx.x], red[threadIdx.x + s]);
        __syncthreads();
    }
    if (threadIdx.x == 0) atomicMax(&g_xmax_bits, __float_as_uint(red[0]));
}

// ---------------------------------------------------------------------------
// 2) fold LoRA into W_eff (fp32) + maxabs
// ---------------------------------------------------------------------------
__global__ __launch_bounds__(256) void fold_kernel(
    const float* __restrict__ W,
    const float* __restrict__ A16, const float* __restrict__ B16,
    const float* __restrict__ A8,  const float* __restrict__ B8,
    const float* __restrict__ A4,  const float* __restrict__ B4,
    const float* __restrict__ A2,  const float* __restrict__ B2,
    const float* __restrict__ A1,  const float* __restrict__ B1,
    const float* __restrict__ alphas)
{
    const int tid   = threadIdx.x;
    const int d0    = (blockIdx.x * 256 + tid) * 4;
    const int obase = blockIdx.y * 16;

    __shared__ float sB[16][32];
    for (int t = tid; t < 16 * 31; t += 256) {
        int ol = t / 31, j = t % 31;
        int o = obase + ol;
        float v;
        if      (j < 16) v = B16[o * 16 + j]       * alphas[0] * 4.0f;
        else if (j < 24) v = B8 [o * 8 + (j - 16)] * alphas[1] * 5.656854249492380f;
        else if (j < 28) v = B4 [o * 4 + (j - 24)] * alphas[2] * 8.0f;
        else if (j < 30) v = B2 [o * 2 + (j - 28)] * alphas[3] * 11.313708498984761f;
        else             v = B1 [o]                * alphas[4] * 16.0f;
        sB[ol][j] = v;
    }
    __syncthreads();

    float4 a[31];
#pragma unroll
    for (int r = 0; r < 16; r++) a[r]      = *(const float4*)(A16 + (size_t)r * DIN + d0);
#pragma unroll
    for (int r = 0; r < 8; r++)  a[16 + r] = *(const float4*)(A8  + (size_t)r * DIN + d0);
#pragma unroll
    for (int r = 0; r < 4; r++)  a[24 + r] = *(const float4*)(A4  + (size_t)r * DIN + d0);
#pragma unroll
    for (int r = 0; r < 2; r++)  a[28 + r] = *(const float4*)(A2  + (size_t)r * DIN + d0);
    a[30] = *(const float4*)(A1 + d0);

    float mx = 0.0f;
#pragma unroll 2
    for (int ol = 0; ol < 16; ol++) {
        int o = obase + ol;
        float4 acc = *(const float4*)(W + (size_t)o * DIN + d0);
#pragma unroll
        for (int j = 0; j < 31; j++) {
            float c = sB[ol][j];
            acc.x = fmaf(c, a[j].x, acc.x);
            acc.y = fmaf(c, a[j].y, acc.y);
            acc.z = fmaf(c, a[j].z, acc.z);
            acc.w = fmaf(c, a[j].w, acc.w);
        }
        *(float4*)(g_wf + (size_t)o * DIN + d0) = acc;
        mx = fmaxf(mx, fmaxf(fmaxf(fabsf(acc.x), fabsf(acc.y)),
                             fmaxf(fabsf(acc.z), fabsf(acc.w))));
    }

    __shared__ float red[256];
    red[tid] = mx;
    __syncthreads();
    for (int s = 128; s > 0; s >>= 1) {
        if (tid < s) red[tid] = fmaxf(red[tid], red[tid + s]);
        __syncthreads();
    }
    if (tid == 0) atomicMax(&g_wmax_bits, __float_as_uint(red[0]));
}

// ---------------------------------------------------------------------------
// 3) quantize to two s8 limbs (14-bit):  V = lrint(v*q); v1=(V+64)>>7; v0=V-128*v1
// ---------------------------------------------------------------------------
__device__ __forceinline__ void quant8(const float* __restrict__ src, size_t i,
                                       float qs, signed char* __restrict__ hi,
                                       signed char* __restrict__ lo) {
    float4 v0 = *(const float4*)(src + i);
    float4 v1 = *(const float4*)(src + i + 4);
    float vv[8] = {v0.x, v0.y, v0.z, v0.w, v1.x, v1.y, v1.z, v1.w};
    uint32_t h0 = 0, h1 = 0, l0 = 0, l1 = 0;
#pragma unroll
    for (int k = 0; k < 8; k++) {
        int X  = __float2int_rn(vv[k] * qs);
        int h  = (X + 64) >> 7;
        int l  = X - (h << 7);
        uint32_t hb = (uint32_t)(h & 0xFF);
        uint32_t lb = (uint32_t)(l & 0xFF);
        if (k < 4) { h0 |= hb << (8 * k);      l0 |= lb << (8 * k); }
        else       { h1 |= hb << (8 * (k - 4)); l1 |= lb << (8 * (k - 4)); }
    }
    *(uint2*)(hi + i) = make_uint2(h0, h1);
    *(uint2*)(lo + i) = make_uint2(l0, l1);
}

__global__ __launch_bounds__(256) void quant_x_kernel(const float* __restrict__ x) {
    size_t i = ((size_t)blockIdx.x * 256 + threadIdx.x) * 8;
    float qs = QMAX / __uint_as_float(g_xmax_bits);
    quant8(x, i, qs, g_x1, g_x0);
}
__global__ __launch_bounds__(256) void quant_w_kernel() {
    size_t i = ((size_t)blockIdx.x * 256 + threadIdx.x) * 8;
    float qs = QMAX / __uint_as_float(g_wmax_bits);
    quant8(g_wf, i, qs, g_w1, g_w0);
}

// ---------------------------------------------------------------------------
// 4) IMMA GEMM
//   CTA 128(M) x 128(N), BK=64 bytes, 3 stages
//   8 warps: grid 2(M) x 4(N), warp tile 64x32
//   per k32 step: 16 IMMA into acc_H (x1*w1), 32 into acc_M (x1*w0 + x0*w1)
// ---------------------------------------------------------------------------
#define BM      128
#define BN      128
#define BK      64
#define NSTAGE  3
#define PITCH   80
#define OFF_X1  0
#define OFF_X0  (128 * PITCH)
#define OFF_W1  (256 * PITCH)
#define OFF_W0  (384 * PITCH)
#define STAGEB  (512 * PITCH)      // 40960
#define NIT     (DIN / BK)         // 64

__global__ __launch_bounds__(256, 1) void gemm_imma(
    const float* __restrict__ bias, float* __restrict__ out)
{
    extern __shared__ char smem[];
    const uint32_t sbase = smem_u32(smem);
    const int tid    = threadIdx.x;
    const int wid    = tid >> 5;
    const int lane   = tid & 31;
    const int warp_m = (wid >> 2) * 64;   // 0 or 64
    const int warp_n = (wid & 3) * 32;    // 0,32,64,96
    const int m0     = blockIdx.y * BM;
    const int n0     = blockIdx.x * BN;

    // loader mapping: 512 rows/stage, thread handles rows tid, tid+256
    const signed char* srcs[2];
    uint32_t dsts[2];
#pragma unroll
    for (int j = 0; j < 2; j++) {
        int r = tid + j * 256;
        const signed char* s;
        uint32_t o;
        if (r < 128)      { s = g_x1 + (size_t)(m0 + r) * DIN;       o = OFF_X1 + r * PITCH; }
        else if (r < 256) { s = g_x0 + (size_t)(m0 + r - 128) * DIN; o = OFF_X0 + (r - 128) * PITCH; }
        else if (r < 384) { s = g_w1 + (size_t)(n0 + r - 256) * DIN; o = OFF_W1 + (r - 256) * PITCH; }
        else              { s = g_w0 + (size_t)(n0 + r - 384) * DIN; o = OFF_W0 + (r - 384) * PITCH; }
        srcs[j] = s;
        dsts[j] = sbase + o;
    }

#define LOAD_STAGE(sidx, kit)                                              \
    do {                                                                   \
        const int kel = (kit) * BK;                                        \
        const uint32_t so = (uint32_t)((sidx) * STAGEB);                   \
        _Pragma("unroll")                                                  \
        for (int j = 0; j < 2; j++) {                                      \
            const signed char* sp = srcs[j] + kel;                         \
            uint32_t dp = dsts[j] + so;                                    \
            cp16(dp,      sp);                                             \
            cp16(dp + 16, sp + 16);                                        \
            cp16(dp + 32, sp + 32);                                        \
            cp16(dp + 48, sp + 48);                                        \
        }                                                                  \
    } while (0)

    // fragment addresses (byte-identical geometry to the bf16 version)
    const uint32_t a_row  = warp_m + (lane & 15);
    const uint32_t a_coff = (lane >> 4) * 16;
    const uint32_t b_row  = warp_n + (lane & 7) + ((lane >> 4) << 3);
    const uint32_t b_coff = ((lane >> 3) & 1) * 16;

    int accH[4][4][4], accM[4][4][4];
#pragma unroll
    for (int i = 0; i < 4; i++)
#pragma unroll
        for (int j = 0; j < 4; j++)
#pragma unroll
            for (int q = 0; q < 4; q++) { accH[i][j][q] = 0; accM[i][j][q] = 0; }

    LOAD_STAGE(0, 0); cp_commit();
    LOAD_STAGE(1, 1); cp_commit();

    for (int it = 0; it < NIT; ++it) {
        cp_wait1();
        __syncthreads();

        const int ps = it + 2;
        if (ps < NIT) LOAD_STAGE(ps % NSTAGE, ps);
        cp_commit();

        const uint32_t sb = sbase + (uint32_t)((it % NSTAGE) * STAGEB);
#pragma unroll
        for (int q = 0; q < 2; q++) {
            const uint32_t kc = q * 32;
            uint32_t xh[4][4], xl[4][4], wh[4][2], wl[4][2];
#pragma unroll
            for (int i = 0; i < 4; i++) {
                uint32_t ad = (a_row + i * 16) * PITCH + kc + a_coff;
                ldsm_x4(xh[i][0], xh[i][1], xh[i][2], xh[i][3], sb + OFF_X1 + ad);
                ldsm_x4(xl[i][0], xl[i][1], xl[i][2], xl[i][3], sb + OFF_X0 + ad);
            }
#pragma unroll
            for (int g = 0; g < 2; g++) {
                uint32_t bd = (b_row + g * 16) * PITCH + kc + b_coff;
                ldsm_x4(wh[2 * g][0], wh[2 * g][1], wh[2 * g + 1][0], wh[2 * g + 1][1],
                        sb + OFF_W1 + bd);
                ldsm_x4(wl[2 * g][0], wl[2 * g][1], wl[2 * g + 1][0], wl[2 * g + 1][1],
                        sb + OFF_W0 + bd);
            }
#pragma unroll
            for (int i = 0; i < 4; i++)
#pragma unroll
                for (int j = 0; j < 4; j++) {
                    imma16832(accH[i][j], xh[i], wh[j]);
                    imma16832(accM[i][j], xh[i], wl[j]);
                    imma16832(accM[i][j], xl[i], wh[j]);
                }
        }
        __syncthreads();
    }

    // epilogue
    const float xm = __uint_as_float(g_xmax_bits);
    const float wm = __uint_as_float(g_wmax_bits);
    const float s  = (xm / QMAX) * (wm / QMAX);
    const float sH = s * 16384.0f;
    const float sM = s * 128.0f;

    const int rbase = m0 + warp_m + (lane >> 2);
    const int cbase = n0 + warp_n + (lane & 3) * 2;
#pragma unroll
    for (int j = 0; j < 4; j++) {
        const int c = cbase + (j >> 1) * 16 + (j & 1) * 8;
        const float2 bv = *(const float2*)(bias + c);
#pragma unroll
        for (int i = 0; i < 4; i++) {
            const int r = rbase + i * 16;
            float2 v0, v1;
            v0.x = sH * (float)accH[i][j][0] + sM * (float)accM[i][j][0] + bv.x;
            v0.y = sH * (float)accH[i][j][1] + sM * (float)accM[i][j][1] + bv.y;
            v1.x = sH * (float)accH[i][j][2] + sM * (float)accM[i][j][2] + bv.x;
            v1.y = sH * (float)accH[i][j][3] + sM * (float)accM[i][j][3] + bv.y;
            *(float2*)(out + (size_t)r * DOUT + c)       = v0;
            *(float2*)(out + (size_t)(r + 8) * DOUT + c) = v1;
        }
    }
}

// ===========================================================================
extern "C" void kernel_launch(void* const* d_in, const int* in_sizes, int n_in,
                              void* d_out, int out_size)
{
    const float* x      = (const float*)d_in[0];
    const float* W      = (const float*)d_in[1];
    const float* b      = (const float*)d_in[2];
    const float* A16    = (const float*)d_in[3];
    const float* B16    = (const float*)d_in[4];
    const float* A8     = (const float*)d_in[5];
    const float* B8     = (const float*)d_in[6];
    const float* A4     = (const float*)d_in[7];
    const float* B4     = (const float*)d_in[8];
    const float* A2     = (const float*)d_in[9];
    const float* B2     = (const float*)d_in[10];
    const float* A1     = (const float*)d_in[11];
    const float* B1     = (const float*)d_in[12];
    const float* alphas = (const float*)d_in[13];
    float* out          = (float*)d_out;

    xmax_kernel<<<2048, 256>>>(x);
    {
        dim3 grid(DIN / (256 * 4), DOUT / 16);
        fold_kernel<<<grid, 256>>>(W, A16, B16, A8, B8, A4, B4, A2, B2, A1, B1, alphas);
    }
    quant_x_kernel<<<(MTOT * DIN) / (256 * 8), 256>>>(x);
    quant_w_kernel<<<(DOUT * DIN) / (256 * 8), 256>>>();
    {
        static bool attr_set = false;
        if (!attr_set) {
            cudaFuncSetAttribute(gemm_imma, cudaFuncAttributeMaxDynamicSharedMemorySize,
                                 NSTAGE * STAGEB);
            attr_set = true;
        }
        dim3 grid(DOUT / BN, MTOT / BM);  // (32, 64)
        gemm_imma<<<grid, 256, NSTAGE * STAGEB>>>(b, out);
    }
}

// round 13
// speedup vs baseline: 5.1317x; 5.1317x over previous
#include <cuda_runtime.h>
#include <cuda_fp16.h>
#include <cstdint>

// MrLoRA: out = x @ (W + sum_i coef_i B_i A_i)^T + b
// Round 13: SINGLE-PASS fp16 HMMA.
//   R12 calibrated the error model (predicted 2-4e-4, measured 2.21e-4).
//   fp16 single pass: per-elem rounding RMS 2^-10/sqrt(12), x&w combined,
//   incoherent over K=4096 -> rel_err ~4e-4 < 1e-3. fp32 accum exact.
//   => delete the hi/lo split entirely: 3x fewer tensor instructions than R3.
// Legacy mma.sync only (harness PTX target compute_103 forbids tcgen05).
// int8 IMMA measured 4x slower per instruction on sm_103a (R12) - not used.

#define DIN   4096
#define DOUT  4096
#define MTOT  8192

// ---- scratch (device globals; allocation-free rule) ----
__device__ __half g_xh[(size_t)MTOT * DIN];
__device__ __half g_wh[(size_t)DOUT * DIN];

// ---------------------------------------------------------------------------
// helpers
// ---------------------------------------------------------------------------
__device__ __forceinline__ uint32_t smem_u32(const void* p) {
    uint32_t a;
    asm("{ .reg .u64 t; cvta.to.shared.u64 t, %1; cvt.u32.u64 %0, t; }"
        : "=r"(a) : "l"(p));
    return a;
}
__device__ __forceinline__ void cp16(uint32_t dst, const void* src) {
    asm volatile("cp.async.cg.shared.global [%0], [%1], 16;"
                 :: "r"(dst), "l"(src) : "memory");
}
__device__ __forceinline__ void cp_commit() {
    asm volatile("cp.async.commit_group;" ::: "memory");
}
__device__ __forceinline__ void cp_wait1() {
    asm volatile("cp.async.wait_group 1;" ::: "memory");
}
__device__ __forceinline__ void ldsm_x4(uint32_t& r0, uint32_t& r1,
                                        uint32_t& r2, uint32_t& r3, uint32_t a) {
    asm volatile("ldmatrix.sync.aligned.m8n8.x4.shared.b16 {%0,%1,%2,%3}, [%4];"
                 : "=r"(r0), "=r"(r1), "=r"(r2), "=r"(r3) : "r"(a));
}
__device__ __forceinline__ void mma16816(float* d, const uint32_t* a,
                                         const uint32_t* b) {
    asm volatile(
        "mma.sync.aligned.m16n8k16.row.col.f32.f16.f16.f32 "
        "{%0,%1,%2,%3}, {%4,%5,%6,%7}, {%8,%9}, {%0,%1,%2,%3};"
        : "+f"(d[0]), "+f"(d[1]), "+f"(d[2]), "+f"(d[3])
        : "r"(a[0]), "r"(a[1]), "r"(a[2]), "r"(a[3]), "r"(b[0]), "r"(b[1]));
}

// ---------------------------------------------------------------------------
// 1) x -> fp16
// ---------------------------------------------------------------------------
__global__ __launch_bounds__(256) void cvt_x_kernel(const float* __restrict__ x) {
    size_t i = ((size_t)blockIdx.x * 256 + threadIdx.x) * 8;
    float4 v0 = *(const float4*)(x + i);
    float4 v1 = *(const float4*)(x + i + 4);
    __half2 h0 = __floats2half2_rn(v0.x, v0.y);
    __half2 h1 = __floats2half2_rn(v0.z, v0.w);
    __half2 h2 = __floats2half2_rn(v1.x, v1.y);
    __half2 h3 = __floats2half2_rn(v1.z, v1.w);
    *(__half2*)(g_xh + i)     = h0;
    *(__half2*)(g_xh + i + 2) = h1;
    *(__half2*)(g_xh + i + 4) = h2;
    *(__half2*)(g_xh + i + 6) = h3;
}

// ---------------------------------------------------------------------------
// 2) fold LoRA into W_eff, emit fp16
// ---------------------------------------------------------------------------
__global__ __launch_bounds__(256) void fold_kernel(
    const float* __restrict__ W,
    const float* __restrict__ A16, const float* __restrict__ B16,
    const float* __restrict__ A8,  const float* __restrict__ B8,
    const float* __restrict__ A4,  const float* __restrict__ B4,
    const float* __restrict__ A2,  const float* __restrict__ B2,
    const float* __restrict__ A1,  const float* __restrict__ B1,
    const float* __restrict__ alphas)
{
    const int tid   = threadIdx.x;
    const int d0    = (blockIdx.x * 256 + tid) * 4;
    const int obase = blockIdx.y * 16;

    __shared__ float sB[16][32];
    for (int t = tid; t < 16 * 31; t += 256) {
        int ol = t / 31, j = t % 31;
        int o = obase + ol;
        float v;
        if      (j < 16) v = B16[o * 16 + j]       * alphas[0] * 4.0f;
        else if (j < 24) v = B8 [o * 8 + (j - 16)] * alphas[1] * 5.656854249492380f;
        else if (j < 28) v = B4 [o * 4 + (j - 24)] * alphas[2] * 8.0f;
        else if (j < 30) v = B2 [o * 2 + (j - 28)] * alphas[3] * 11.313708498984761f;
        else             v = B1 [o]                * alphas[4] * 16.0f;
        sB[ol][j] = v;
    }
    __syncthreads();

    float4 a[31];
#pragma unroll
    for (int r = 0; r < 16; r++) a[r]      = *(const float4*)(A16 + (size_t)r * DIN + d0);
#pragma unroll
    for (int r = 0; r < 8; r++)  a[16 + r] = *(const float4*)(A8  + (size_t)r * DIN + d0);
#pragma unroll
    for (int r = 0; r < 4; r++)  a[24 + r] = *(const float4*)(A4  + (size_t)r * DIN + d0);
#pragma unroll
    for (int r = 0; r < 2; r++)  a[28 + r] = *(const float4*)(A2  + (size_t)r * DIN + d0);
    a[30] = *(const float4*)(A1 + d0);

#pragma unroll 2
    for (int ol = 0; ol < 16; ol++) {
        int o = obase + ol;
        float4 acc = *(const float4*)(W + (size_t)o * DIN + d0);
#pragma unroll
        for (int j = 0; j < 31; j++) {
            float c = sB[ol][j];
            acc.x = fmaf(c, a[j].x, acc.x);
            acc.y = fmaf(c, a[j].y, acc.y);
            acc.z = fmaf(c, a[j].z, acc.z);
            acc.w = fmaf(c, a[j].w, acc.w);
        }
        size_t off = (size_t)o * DIN + d0;
        *(__half2*)(g_wh + off)     = __floats2half2_rn(acc.x, acc.y);
        *(__half2*)(g_wh + off + 2) = __floats2half2_rn(acc.z, acc.w);
    }
}

// ---------------------------------------------------------------------------
// 3) fp16 HMMA GEMM (single pass)
//   CTA 128(M) x 256(N), BK=32, 3 stages
//   8 warps: grid 2(M) x 4(N), warp tile 64x64
//   smem rows: 32 fp16 = 64B + 16B pad -> PITCH 80, conflict-free ldmatrix
// ---------------------------------------------------------------------------
#define BM      128
#define BN      256
#define BK      32
#define NSTAGE  3
#define PITCH   80
#define OFF_A   0
#define OFF_B   (128 * PITCH)          // 10240
#define STAGEB  (384 * PITCH)          // 30720
#define NIT     (DIN / BK)             // 128

__global__ __launch_bounds__(256, 1) void gemm_hmma(
    const float* __restrict__ bias, float* __restrict__ out)
{
    extern __shared__ char smem[];
    const uint32_t sbase = smem_u32(smem);
    const int tid    = threadIdx.x;
    const int wid    = tid >> 5;
    const int lane   = tid & 31;
    const int warp_m = (wid >> 2) * 64;   // 0 or 64
    const int warp_n = (wid & 3) * 64;    // 0,64,128,192
    const int m0     = blockIdx.y * BM;
    const int n0     = blockIdx.x * BN;

    // loader mapping: 384 rows/stage (128 x-rows + 256 w-rows), 64B each.
    // thread t handles row t (j=0) and, if t<128, row 256+t (j=1).
    const __half* srcs[2];
    uint32_t dsts[2];
    int nrows = 1;
    {
        int r0 = tid;
        if (r0 < 128) { srcs[0] = g_xh + (size_t)(m0 + r0) * DIN;       dsts[0] = sbase + OFF_A + r0 * PITCH; }
        else          { srcs[0] = g_wh + (size_t)(n0 + r0 - 128) * DIN; dsts[0] = sbase + OFF_B + (r0 - 128) * PITCH; }
        if (tid < 128) {
            int r1 = 256 + tid;  // w rows 128..255
            srcs[1] = g_wh + (size_t)(n0 + r1 - 128) * DIN;
            dsts[1] = sbase + OFF_B + (r1 - 128) * PITCH;
            nrows = 2;
        }
    }

#define LOAD_STAGE(sidx, kit)                                              \
    do {                                                                   \
        const int kel = (kit) * BK;                                        \
        const uint32_t so = (uint32_t)((sidx) * STAGEB);                   \
        for (int j = 0; j < nrows; j++) {                                  \
            const __half* sp = srcs[j] + kel;                              \
            uint32_t dp = dsts[j] + so;                                    \
            cp16(dp,      sp);                                             \
            cp16(dp + 16, sp + 8);                                         \
            cp16(dp + 32, sp + 16);                                        \
            cp16(dp + 48, sp + 24);                                        \
        }                                                                  \
    } while (0)

    // fragment smem addresses (per k16 step q: byte offset q*32 within row)
    const uint32_t a_row  = warp_m + (lane & 15);
    const uint32_t a_coff = (lane >> 4) * 16;
    const uint32_t b_row  = warp_n + (lane & 7) + ((lane >> 4) << 3);
    const uint32_t b_coff = ((lane >> 3) & 1) * 16;

    float acc[4][8][4];
#pragma unroll
    for (int i = 0; i < 4; i++)
#pragma unroll
        for (int j = 0; j < 8; j++)
#pragma unroll
            for (int q = 0; q < 4; q++) acc[i][j][q] = 0.0f;

    LOAD_STAGE(0, 0); cp_commit();
    LOAD_STAGE(1, 1); cp_commit();

    for (int it = 0; it < NIT; ++it) {
        cp_wait1();
        __syncthreads();

        const int ps = it + 2;
        if (ps < NIT) LOAD_STAGE(ps % NSTAGE, ps);
        cp_commit();

        const uint32_t sb = sbase + (uint32_t)((it % NSTAGE) * STAGEB);
#pragma unroll
        for (int q = 0; q < 2; q++) {
            const uint32_t kc = q * 32;
            uint32_t aF[4][4], bF[8][2];
#pragma unroll
            for (int i = 0; i < 4; i++) {
                uint32_t ad = (a_row + i * 16) * PITCH + kc + a_coff;
                ldsm_x4(aF[i][0], aF[i][1], aF[i][2], aF[i][3], sb + OFF_A + ad);
            }
#pragma unroll
            for (int g = 0; g < 4; g++) {
                uint32_t bd = (b_row + g * 16) * PITCH + kc + b_coff;
                ldsm_x4(bF[2 * g][0], bF[2 * g][1], bF[2 * g + 1][0], bF[2 * g + 1][1],
                        sb + OFF_B + bd);
            }
#pragma unroll
            for (int i = 0; i < 4; i++)
#pragma unroll
                for (int j = 0; j < 8; j++)
                    mma16816(acc[i][j], aF[i], bF[j]);
        }
        __syncthreads();
    }

    // epilogue: acc -> gmem with bias
    const int rbase = m0 + warp_m + (lane >> 2);
    const int cbase = n0 + warp_n + (lane & 3) * 2;
#pragma unroll
    for (int j = 0; j < 8; j++) {
        const int c = cbase + j * 8;
        const float2 bv = *(const float2*)(bias + c);
#pragma unroll
        for (int i = 0; i < 4; i++) {
            const int r = rbase + i * 16;
            float2 v0, v1;
            v0.x = acc[i][j][0] + bv.x; v0.y = acc[i][j][1] + bv.y;
            v1.x = acc[i][j][2] + bv.x; v1.y = acc[i][j][3] + bv.y;
            *(float2*)(out + (size_t)r * DOUT + c)       = v0;
            *(float2*)(out + (size_t)(r + 8) * DOUT + c) = v1;
        }
    }
}

// ===========================================================================
extern "C" void kernel_launch(void* const* d_in, const int* in_sizes, int n_in,
                              void* d_out, int out_size)
{
    const float* x      = (const float*)d_in[0];
    const float* W      = (const float*)d_in[1];
    const float* b      = (const float*)d_in[2];
    const float* A16    = (const float*)d_in[3];
    const float* B16    = (const float*)d_in[4];
    const float* A8     = (const float*)d_in[5];
    const float* B8     = (const float*)d_in[6];
    const float* A4     = (const float*)d_in[7];
    const float* B4     = (const float*)d_in[8];
    const float* A2     = (const float*)d_in[9];
    const float* B2     = (const float*)d_in[10];
    const float* A1     = (const float*)d_in[11];
    const float* B1     = (const float*)d_in[12];
    const float* alphas = (const float*)d_in[13];
    float* out          = (float*)d_out;

    cvt_x_kernel<<<(MTOT * DIN) / (256 * 8), 256>>>(x);
    {
        dim3 grid(DIN / (256 * 4), DOUT / 16);
        fold_kernel<<<grid, 256>>>(W, A16, B16, A8, B8, A4, B4, A2, B2, A1, B1, alphas);
    }
    {
        static bool attr_set = false;
        if (!attr_set) {
            cudaFuncSetAttribute(gemm_hmma, cudaFuncAttributeMaxDynamicSharedMemorySize,
                                 NSTAGE * STAGEB);
            attr_set = true;
        }
        dim3 grid(DOUT / BN, MTOT / BM);  // (16, 64)
        gemm_hmma<<<grid, 256, NSTAGE * STAGEB>>>(b, out);
    }
}

// round 15
// speedup vs baseline: 7.0612x; 1.3760x over previous
#include <cuda_runtime.h>
#include <cuda_fp16.h>
#include <cstdint>

// MrLoRA: out = x @ (W + sum_i coef_i B_i A_i)^T + b
// Round 14 (resubmit): single-pass fp16 HMMA (R13 math), scheduling improved:
//   512 threads/CTA (16 warps, 4/SMSP), warp tile 64x32 (acc 64 regs),
//   4-stage cp.async pipeline. Same CTA tile 128x256, same HMMA count.
// Legacy mma.sync only (compute_103 PTX target forbids tcgen05).
// int8 IMMA measured 4x slower/instr (R12) - not used.

#define DIN   4096
#define DOUT  4096
#define MTOT  8192

__device__ __half g_xh[(size_t)MTOT * DIN];
__device__ __half g_wh[(size_t)DOUT * DIN];

// ---------------------------------------------------------------------------
__device__ __forceinline__ uint32_t smem_u32(const void* p) {
    uint32_t a;
    asm("{ .reg .u64 t; cvta.to.shared.u64 t, %1; cvt.u32.u64 %0, t; }"
        : "=r"(a) : "l"(p));
    return a;
}
__device__ __forceinline__ void cp16(uint32_t dst, const void* src) {
    asm volatile("cp.async.cg.shared.global [%0], [%1], 16;"
                 :: "r"(dst), "l"(src) : "memory");
}
__device__ __forceinline__ void cp_commit() {
    asm volatile("cp.async.commit_group;" ::: "memory");
}
__device__ __forceinline__ void cp_wait2() {
    asm volatile("cp.async.wait_group 2;" ::: "memory");
}
__device__ __forceinline__ void ldsm_x4(uint32_t& r0, uint32_t& r1,
                                        uint32_t& r2, uint32_t& r3, uint32_t a) {
    asm volatile("ldmatrix.sync.aligned.m8n8.x4.shared.b16 {%0,%1,%2,%3}, [%4];"
                 : "=r"(r0), "=r"(r1), "=r"(r2), "=r"(r3) : "r"(a));
}
__device__ __forceinline__ void mma16816(float* d, const uint32_t* a,
                                         const uint32_t* b) {
    asm volatile(
        "mma.sync.aligned.m16n8k16.row.col.f32.f16.f16.f32 "
        "{%0,%1,%2,%3}, {%4,%5,%6,%7}, {%8,%9}, {%0,%1,%2,%3};"
        : "+f"(d[0]), "+f"(d[1]), "+f"(d[2]), "+f"(d[3])
        : "r"(a[0]), "r"(a[1]), "r"(a[2]), "r"(a[3]), "r"(b[0]), "r"(b[1]));
}

// ---------------------------------------------------------------------------
// 1) x -> fp16
// ---------------------------------------------------------------------------
__global__ __launch_bounds__(256) void cvt_x_kernel(const float* __restrict__ x) {
    size_t i = ((size_t)blockIdx.x * 256 + threadIdx.x) * 8;
    float4 v0 = *(const float4*)(x + i);
    float4 v1 = *(const float4*)(x + i + 4);
    *(__half2*)(g_xh + i)     = __floats2half2_rn(v0.x, v0.y);
    *(__half2*)(g_xh + i + 2) = __floats2half2_rn(v0.z, v0.w);
    *(__half2*)(g_xh + i + 4) = __floats2half2_rn(v1.x, v1.y);
    *(__half2*)(g_xh + i + 6) = __floats2half2_rn(v1.z, v1.w);
}

// ---------------------------------------------------------------------------
// 2) fold LoRA into W_eff, emit fp16
// ---------------------------------------------------------------------------
__global__ __launch_bounds__(256) void fold_kernel(
    const float* __restrict__ W,
    const float* __restrict__ A16, const float* __restrict__ B16,
    const float* __restrict__ A8,  const float* __restrict__ B8,
    const float* __restrict__ A4,  const float* __restrict__ B4,
    const float* __restrict__ A2,  const float* __restrict__ B2,
    const float* __restrict__ A1,  const float* __restrict__ B1,
    const float* __restrict__ alphas)
{
    const int tid   = threadIdx.x;
    const int d0    = (blockIdx.x * 256 + tid) * 4;
    const int obase = blockIdx.y * 16;

    __shared__ float sB[16][32];
    for (int t = tid; t < 16 * 31; t += 256) {
        int ol = t / 31, j = t % 31;
        int o = obase + ol;
        float v;
        if      (j < 16) v = B16[o * 16 + j]       * alphas[0] * 4.0f;
        else if (j < 24) v = B8 [o * 8 + (j - 16)] * alphas[1] * 5.656854249492380f;
        else if (j < 28) v = B4 [o * 4 + (j - 24)] * alphas[2] * 8.0f;
        else if (j < 30) v = B2 [o * 2 + (j - 28)] * alphas[3] * 11.313708498984761f;
        else             v = B1 [o]                * alphas[4] * 16.0f;
        sB[ol][j] = v;
    }
    __syncthreads();

    float4 a[31];
#pragma unroll
    for (int r = 0; r < 16; r++) a[r]      = *(const float4*)(A16 + (size_t)r * DIN + d0);
#pragma unroll
    for (int r = 0; r < 8; r++)  a[16 + r] = *(const float4*)(A8  + (size_t)r * DIN + d0);
#pragma unroll
    for (int r = 0; r < 4; r++)  a[24 + r] = *(const float4*)(A4  + (size_t)r * DIN + d0);
#pragma unroll
    for (int r = 0; r < 2; r++)  a[28 + r] = *(const float4*)(A2  + (size_t)r * DIN + d0);
    a[30] = *(const float4*)(A1 + d0);

#pragma unroll 2
    for (int ol = 0; ol < 16; ol++) {
        int o = obase + ol;
        float4 acc = *(const float4*)(W + (size_t)o * DIN + d0);
#pragma unroll
        for (int j = 0; j < 31; j++) {
            float c = sB[ol][j];
            acc.x = fmaf(c, a[j].x, acc.x);
            acc.y = fmaf(c, a[j].y, acc.y);
            acc.z = fmaf(c, a[j].z, acc.z);
            acc.w = fmaf(c, a[j].w, acc.w);
        }
        size_t off = (size_t)o * DIN + d0;
        *(__half2*)(g_wh + off)     = __floats2half2_rn(acc.x, acc.y);
        *(__half2*)(g_wh + off + 2) = __floats2half2_rn(acc.z, acc.w);
    }
}

// ---------------------------------------------------------------------------
// 3) fp16 HMMA GEMM
//   CTA 128(M) x 256(N), BK=32, 4 stages, 512 threads (16 warps)
//   warp grid 2(M) x 8(N), warp tile 64x32
//   smem rows: 32 fp16 = 64B + 16B pad -> PITCH 80, conflict-free ldmatrix
// ---------------------------------------------------------------------------
#define BM      128
#define BN      256
#define BK      32
#define NSTAGE  4
#define PITCH   80
#define OFF_A   0
#define OFF_B   (128 * PITCH)          // 10240
#define STAGEB  (384 * PITCH)          // 30720
#define NIT     (DIN / BK)             // 128

__global__ __launch_bounds__(512, 1) void gemm_hmma(
    const float* __restrict__ bias, float* __restrict__ out)
{
    extern __shared__ char smem[];
    const uint32_t sbase = smem_u32(smem);
    const int tid    = threadIdx.x;
    const int wid    = tid >> 5;
    const int lane   = tid & 31;
    const int warp_m = (wid >> 3) * 64;   // 0 or 64
    const int warp_n = (wid & 7) * 32;    // 0..224
    const int m0     = blockIdx.y * BM;
    const int n0     = blockIdx.x * BN;

    // loader: 384 rows/stage * 4 16B-chunks = 1536 chunks; thread handles
    // chunks tid, tid+512, tid+1024.
    const __half* lsrc[3];
    uint32_t ldst[3];
#pragma unroll
    for (int j = 0; j < 3; j++) {
        int chunk = tid + j * 512;
        int r     = chunk >> 2;            // 0..383
        int co    = chunk & 3;             // 16B chunk within row
        if (r < 128) {
            lsrc[j] = g_xh + (size_t)(m0 + r) * DIN + co * 8;
            ldst[j] = sbase + OFF_A + r * PITCH + co * 16;
        } else {
            lsrc[j] = g_wh + (size_t)(n0 + r - 128) * DIN + co * 8;
            ldst[j] = sbase + OFF_B + (r - 128) * PITCH + co * 16;
        }
    }

#define LOAD_STAGE(sidx, kit)                                              \
    do {                                                                   \
        const int kel = (kit) * BK;                                        \
        const uint32_t so = (uint32_t)((sidx) * STAGEB);                   \
        _Pragma("unroll")                                                  \
        for (int j = 0; j < 3; j++)                                        \
            cp16(ldst[j] + so, lsrc[j] + kel);                             \
    } while (0)

    // fragment smem addresses (per k16 step q: byte offset q*32 within row)
    const uint32_t a_row  = warp_m + (lane & 15);
    const uint32_t a_coff = (lane >> 4) * 16;
    const uint32_t b_row  = warp_n + (lane & 7) + ((lane >> 4) << 3);
    const uint32_t b_coff = ((lane >> 3) & 1) * 16;

    float acc[4][4][4];
#pragma unroll
    for (int i = 0; i < 4; i++)
#pragma unroll
        for (int j = 0; j < 4; j++)
#pragma unroll
            for (int q = 0; q < 4; q++) acc[i][j][q] = 0.0f;

    LOAD_STAGE(0, 0); cp_commit();
    LOAD_STAGE(1, 1); cp_commit();
    LOAD_STAGE(2, 2); cp_commit();

    for (int it = 0; it < NIT; ++it) {
        cp_wait2();
        __syncthreads();

        const int ps = it + 3;
        if (ps < NIT) LOAD_STAGE(ps % NSTAGE, ps);
        cp_commit();

        const uint32_t sb = sbase + (uint32_t)((it % NSTAGE) * STAGEB);
#pragma unroll
        for (int q = 0; q < 2; q++) {
            const uint32_t kc = q * 32;
            uint32_t aF[4][4], bF[4][2];
#pragma unroll
            for (int i = 0; i < 4; i++) {
                uint32_t ad = (a_row + i * 16) * PITCH + kc + a_coff;
                ldsm_x4(aF[i][0], aF[i][1], aF[i][2], aF[i][3], sb + OFF_A + ad);
            }
#pragma unroll
            for (int g = 0; g < 2; g++) {
                uint32_t bd = (b_row + g * 16) * PITCH + kc + b_coff;
                ldsm_x4(bF[2 * g][0], bF[2 * g][1], bF[2 * g + 1][0], bF[2 * g + 1][1],
                        sb + OFF_B + bd);
            }
#pragma unroll
            for (int i = 0; i < 4; i++)
#pragma unroll
                for (int j = 0; j < 4; j++)
                    mma16816(acc[i][j], aF[i], bF[j]);
        }
        __syncthreads();
    }

    // epilogue
    const int rbase = m0 + warp_m + (lane >> 2);
    const int cbase = n0 + warp_n + (lane & 3) * 2;
#pragma unroll
    for (int j = 0; j < 4; j++) {
        const int c = cbase + j * 8;
        const float2 bv = *(const float2*)(bias + c);
#pragma unroll
        for (int i = 0; i < 4; i++) {
            const int r = rbase + i * 16;
            float2 v0, v1;
            v0.x = acc[i][j][0] + bv.x; v0.y = acc[i][j][1] + bv.y;
            v1.x = acc[i][j][2] + bv.x; v1.y = acc[i][j][3] + bv.y;
            *(float2*)(out + (size_t)r * DOUT + c)       = v0;
            *(float2*)(out + (size_t)(r + 8) * DOUT + c) = v1;
        }
    }
}

// ===========================================================================
extern "C" void kernel_launch(void* const* d_in, const int* in_sizes, int n_in,
                              void* d_out, int out_size)
{
    const float* x      = (const float*)d_in[0];
    const float* W      = (const float*)d_in[1];
    const float* b      = (const float*)d_in[2];
    const float* A16    = (const float*)d_in[3];
    const float* B16    = (const float*)d_in[4];
    const float* A8     = (const float*)d_in[5];
    const float* B8     = (const float*)d_in[6];
    const float* A4     = (const float*)d_in[7];
    const float* B4     = (const float*)d_in[8];
    const float* A2     = (const float*)d_in[9];
    const float* B2     = (const float*)d_in[10];
    const float* A1     = (const float*)d_in[11];
    const float* B1     = (const float*)d_in[12];
    const float* alphas = (const float*)d_in[13];
    float* out          = (float*)d_out;

    cvt_x_kernel<<<(MTOT * DIN) / (256 * 8), 256>>>(x);
    {
        dim3 grid(DIN / (256 * 4), DOUT / 16);
        fold_kernel<<<grid, 256>>>(W, A16, B16, A8, B8, A4, B4, A2, B2, A1, B1, alphas);
    }
    {
        static bool attr_set = false;
        if (!attr_set) {
            cudaFuncSetAttribute(gemm_hmma, cudaFuncAttributeMaxDynamicSharedMemorySize,
                                 NSTAGE * STAGEB);
            attr_set = true;
        }
        dim3 grid(DOUT / BN, MTOT / BM);  // (16, 64)
        gemm_hmma<<<grid, 512, NSTAGE * STAGEB>>>(b, out);
    }
}

// round 16
// speedup vs baseline: 7.1872x; 1.0178x over previous
#include <cuda_runtime.h>
#include <cuda_fp16.h>
#include <cstdint>

// MrLoRA: out = x @ (W + sum_i coef_i B_i A_i)^T + b
// Round 16: single-pass fp16 HMMA; 2 CTAs/SM to decouple barriers.
//   CTA 128x128, 256 threads (8 warps, warp tile 64x32), 4-stage cp.async,
//   __launch_bounds__(256,2): two independent CTAs per SM interleave so one
//   CTA's bar.sync no longer drains the whole SM.
// Legacy mma.sync only (compute_103 PTX target forbids tcgen05).
// int8 IMMA measured 4x slower/instr (R12) - not used.

#define DIN   4096
#define DOUT  4096
#define MTOT  8192

__device__ __half g_xh[(size_t)MTOT * DIN];
__device__ __half g_wh[(size_t)DOUT * DIN];

// ---------------------------------------------------------------------------
__device__ __forceinline__ uint32_t smem_u32(const void* p) {
    uint32_t a;
    asm("{ .reg .u64 t; cvta.to.shared.u64 t, %1; cvt.u32.u64 %0, t; }"
        : "=r"(a) : "l"(p));
    return a;
}
__device__ __forceinline__ void cp16(uint32_t dst, const void* src) {
    asm volatile("cp.async.cg.shared.global [%0], [%1], 16;"
                 :: "r"(dst), "l"(src) : "memory");
}
__device__ __forceinline__ void cp_commit() {
    asm volatile("cp.async.commit_group;" ::: "memory");
}
__device__ __forceinline__ void cp_wait2() {
    asm volatile("cp.async.wait_group 2;" ::: "memory");
}
__device__ __forceinline__ void ldsm_x4(uint32_t& r0, uint32_t& r1,
                                        uint32_t& r2, uint32_t& r3, uint32_t a) {
    asm volatile("ldmatrix.sync.aligned.m8n8.x4.shared.b16 {%0,%1,%2,%3}, [%4];"
                 : "=r"(r0), "=r"(r1), "=r"(r2), "=r"(r3) : "r"(a));
}
__device__ __forceinline__ void mma16816(float* d, const uint32_t* a,
                                         const uint32_t* b) {
    asm volatile(
        "mma.sync.aligned.m16n8k16.row.col.f32.f16.f16.f32 "
        "{%0,%1,%2,%3}, {%4,%5,%6,%7}, {%8,%9}, {%0,%1,%2,%3};"
        : "+f"(d[0]), "+f"(d[1]), "+f"(d[2]), "+f"(d[3])
        : "r"(a[0]), "r"(a[1]), "r"(a[2]), "r"(a[3]), "r"(b[0]), "r"(b[1]));
}

// ---------------------------------------------------------------------------
// 1) x -> fp16
// ---------------------------------------------------------------------------
__global__ __launch_bounds__(256) void cvt_x_kernel(const float* __restrict__ x) {
    size_t i = ((size_t)blockIdx.x * 256 + threadIdx.x) * 8;
    float4 v0 = *(const float4*)(x + i);
    float4 v1 = *(const float4*)(x + i + 4);
    *(__half2*)(g_xh + i)     = __floats2half2_rn(v0.x, v0.y);
    *(__half2*)(g_xh + i + 2) = __floats2half2_rn(v0.z, v0.w);
    *(__half2*)(g_xh + i + 4) = __floats2half2_rn(v1.x, v1.y);
    *(__half2*)(g_xh + i + 6) = __floats2half2_rn(v1.z, v1.w);
}

// ---------------------------------------------------------------------------
// 2) fold LoRA into W_eff, emit fp16
// ---------------------------------------------------------------------------
__global__ __launch_bounds__(256) void fold_kernel(
    const float* __restrict__ W,
    const float* __restrict__ A16, const float* __restrict__ B16,
    const float* __restrict__ A8,  const float* __restrict__ B8,
    const float* __restrict__ A4,  const float* __restrict__ B4,
    const float* __restrict__ A2,  const float* __restrict__ B2,
    const float* __restrict__ A1,  const float* __restrict__ B1,
    const float* __restrict__ alphas)
{
    const int tid   = threadIdx.x;
    const int d0    = (blockIdx.x * 256 + tid) * 4;
    const int obase = blockIdx.y * 16;

    __shared__ float sB[16][32];
    for (int t = tid; t < 16 * 31; t += 256) {
        int ol = t / 31, j = t % 31;
        int o = obase + ol;
        float v;
        if      (j < 16) v = B16[o * 16 + j]       * alphas[0] * 4.0f;
        else if (j < 24) v = B8 [o * 8 + (j - 16)] * alphas[1] * 5.656854249492380f;
        else if (j < 28) v = B4 [o * 4 + (j - 24)] * alphas[2] * 8.0f;
        else if (j < 30) v = B2 [o * 2 + (j - 28)] * alphas[3] * 11.313708498984761f;
        else             v = B1 [o]                * alphas[4] * 16.0f;
        sB[ol][j] = v;
    }
    __syncthreads();

    float4 a[31];
#pragma unroll
    for (int r = 0; r < 16; r++) a[r]      = *(const float4*)(A16 + (size_t)r * DIN + d0);
#pragma unroll
    for (int r = 0; r < 8; r++)  a[16 + r] = *(const float4*)(A8  + (size_t)r * DIN + d0);
#pragma unroll
    for (int r = 0; r < 4; r++)  a[24 + r] = *(const float4*)(A4  + (size_t)r * DIN + d0);
#pragma unroll
    for (int r = 0; r < 2; r++)  a[28 + r] = *(const float4*)(A2  + (size_t)r * DIN + d0);
    a[30] = *(const float4*)(A1 + d0);

#pragma unroll 2
    for (int ol = 0; ol < 16; ol++) {
        int o = obase + ol;
        float4 acc = *(const float4*)(W + (size_t)o * DIN + d0);
#pragma unroll
        for (int j = 0; j < 31; j++) {
            float c = sB[ol][j];
            acc.x = fmaf(c, a[j].x, acc.x);
            acc.y = fmaf(c, a[j].y, acc.y);
            acc.z = fmaf(c, a[j].z, acc.z);
            acc.w = fmaf(c, a[j].w, acc.w);
        }
        size_t off = (size_t)o * DIN + d0;
        *(__half2*)(g_wh + off)     = __floats2half2_rn(acc.x, acc.y);
        *(__half2*)(g_wh + off + 2) = __floats2half2_rn(acc.z, acc.w);
    }
}

// ---------------------------------------------------------------------------
// 3) fp16 HMMA GEMM
//   CTA 128(M) x 128(N), BK=32, 4 stages, 256 threads (8 warps), 2 CTAs/SM
//   warp grid 2(M) x 4(N), warp tile 64x32
//   smem rows: 32 fp16 = 64B + 16B pad -> PITCH 80, conflict-free ldmatrix
// ---------------------------------------------------------------------------
#define BM      128
#define BN      128
#define BK      32
#define NSTAGE  4
#define PITCH   80
#define OFF_A   0
#define OFF_B   (128 * PITCH)          // 10240
#define STAGEB  (256 * PITCH)          // 20480
#define NIT     (DIN / BK)             // 128

__global__ __launch_bounds__(256, 2) void gemm_hmma(
    const float* __restrict__ bias, float* __restrict__ out)
{
    extern __shared__ char smem[];
    const uint32_t sbase = smem_u32(smem);
    const int tid    = threadIdx.x;
    const int wid    = tid >> 5;
    const int lane   = tid & 31;
    const int warp_m = (wid >> 2) * 64;   // 0 or 64
    const int warp_n = (wid & 3) * 32;    // 0,32,64,96
    const int m0     = blockIdx.y * BM;
    const int n0     = blockIdx.x * BN;

    // loader: 256 rows/stage * 4 16B-chunks = 1024 chunks / 256 threads = 4 each
    const __half* lsrc[4];
    uint32_t ldst[4];
#pragma unroll
    for (int j = 0; j < 4; j++) {
        int chunk = tid + j * 256;
        int r     = chunk >> 2;            // 0..255
        int co    = chunk & 3;             // 16B chunk within row
        if (r < 128) {
            lsrc[j] = g_xh + (size_t)(m0 + r) * DIN + co * 8;
            ldst[j] = sbase + OFF_A + r * PITCH + co * 16;
        } else {
            lsrc[j] = g_wh + (size_t)(n0 + r - 128) * DIN + co * 8;
            ldst[j] = sbase + OFF_B + (r - 128) * PITCH + co * 16;
        }
    }

#define LOAD_STAGE(sidx, kit)                                              \
    do {                                                                   \
        const int kel = (kit) * BK;                                        \
        const uint32_t so = (uint32_t)((sidx) * STAGEB);                   \
        _Pragma("unroll")                                                  \
        for (int j = 0; j < 4; j++)                                        \
            cp16(ldst[j] + so, lsrc[j] + kel);                             \
    } while (0)

    // fragment smem addresses (per k16 step q: byte offset q*32 within row)
    const uint32_t a_row  = warp_m + (lane & 15);
    const uint32_t a_coff = (lane >> 4) * 16;
    const uint32_t b_row  = warp_n + (lane & 7) + ((lane >> 4) << 3);
    const uint32_t b_coff = ((lane >> 3) & 1) * 16;

    float acc[4][4][4];
#pragma unroll
    for (int i = 0; i < 4; i++)
#pragma unroll
        for (int j = 0; j < 4; j++)
#pragma unroll
            for (int q = 0; q < 4; q++) acc[i][j][q] = 0.0f;

    LOAD_STAGE(0, 0); cp_commit();
    LOAD_STAGE(1, 1); cp_commit();
    LOAD_STAGE(2, 2); cp_commit();

    for (int it = 0; it < NIT; ++it) {
        cp_wait2();
        __syncthreads();

        const int ps = it + 3;
        if (ps < NIT) LOAD_STAGE(ps % NSTAGE, ps);
        cp_commit();

        const uint32_t sb = sbase + (uint32_t)((it % NSTAGE) * STAGEB);
#pragma unroll
        for (int q = 0; q < 2; q++) {
            const uint32_t kc = q * 32;
            uint32_t aF[4][4], bF[4][2];
#pragma unroll
            for (int i = 0; i < 4; i++) {
                uint32_t ad = (a_row + i * 16) * PITCH + kc + a_coff;
                ldsm_x4(aF[i][0], aF[i][1], aF[i][2], aF[i][3], sb + OFF_A + ad);
            }
#pragma unroll
            for (int g = 0; g < 2; g++) {
                uint32_t bd = (b_row + g * 16) * PITCH + kc + b_coff;
                ldsm_x4(bF[2 * g][0], bF[2 * g][1], bF[2 * g + 1][0], bF[2 * g + 1][1],
                        sb + OFF_B + bd);
            }
#pragma unroll
            for (int i = 0; i < 4; i++)
#pragma unroll
                for (int j = 0; j < 4; j++)
                    mma16816(acc[i][j], aF[i], bF[j]);
        }
        __syncthreads();
    }

    // epilogue
    const int rbase = m0 + warp_m + (lane >> 2);
    const int cbase = n0 + warp_n + (lane & 3) * 2;
#pragma unroll
    for (int j = 0; j < 4; j++) {
        const int c = cbase + j * 8;
        const float2 bv = *(const float2*)(bias + c);
#pragma unroll
        for (int i = 0; i < 4; i++) {
            const int r = rbase + i * 16;
            float2 v0, v1;
            v0.x = acc[i][j][0] + bv.x; v0.y = acc[i][j][1] + bv.y;
            v1.x = acc[i][j][2] + bv.x; v1.y = acc[i][j][3] + bv.y;
            *(float2*)(out + (size_t)r * DOUT + c)       = v0;
            *(float2*)(out + (size_t)(r + 8) * DOUT + c) = v1;
        }
    }
}

// ===========================================================================
extern "C" void kernel_launch(void* const* d_in, const int* in_sizes, int n_in,
                              void* d_out, int out_size)
{
    const float* x      = (const float*)d_in[0];
    const float* W      = (const float*)d_in[1];
    const float* b      = (const float*)d_in[2];
    const float* A16    = (const float*)d_in[3];
    const float* B16    = (const float*)d_in[4];
    const float* A8     = (const float*)d_in[5];
    const float* B8     = (const float*)d_in[6];
    const float* A4     = (const float*)d_in[7];
    const float* B4     = (const float*)d_in[8];
    const float* A2     = (const float*)d_in[9];
    const float* B2     = (const float*)d_in[10];
    const float* A1     = (const float*)d_in[11];
    const float* B1     = (const float*)d_in[12];
    const float* alphas = (const float*)d_in[13];
    float* out          = (float*)d_out;

    cvt_x_kernel<<<(MTOT * DIN) / (256 * 8), 256>>>(x);
    {
        dim3 grid(DIN / (256 * 4), DOUT / 16);
        fold_kernel<<<grid, 256>>>(W, A16, B16, A8, B8, A4, B4, A2, B2, A1, B1, alphas);
    }
    {
        static bool attr_set = false;
        if (!attr_set) {
            cudaFuncSetAttribute(gemm_hmma, cudaFuncAttributeMaxDynamicSharedMemorySize,
                                 NSTAGE * STAGEB);
            attr_set = true;
        }
        dim3 grid(DOUT / BN, MTOT / BM);  // (32, 64)
        gemm_hmma<<<grid, 256, NSTAGE * STAGEB>>>(b, out);
    }
}